// round 3
// baseline (speedup 1.0000x reference)
#include <cuda_runtime.h>
#include <math.h>

#ifndef M_PI
#define M_PI 3.14159265358979323846
#endif

// Half-slice tile with clamp-to-zero guards:
//   rows: 0,1 zero | 2..130 data | 131,132 zero   (133 rows)
//   cols: 0,1 zero | 2..257 data | 258,259 zero | 260 pad (261 ~ odd mod 32)
// Phase 0: tile row t = vol row (t-2),  owned floors -1..127  (trow 1..129)
// Phase 1: tile row t = vol row (t+126), owned floors 128..255 (trow 2..129)
// Seam leak rows killed by predicate: phase0 trow==130, phase1 trow==1.
#define TS    261
#define TROWS 133
#define TILE_BYTES (TROWS * TS * 4)

typedef unsigned long long ull;

#define FMA2(d,a,b,c) asm("fma.rn.f32x2 %0, %1, %2, %3;" : "=l"(d) : "l"(a), "l"(b), "l"(c))
#define ADD2(d,a,b)   asm("add.rn.f32x2 %0, %1, %2;"     : "=l"(d) : "l"(a), "l"(b))
#define PK2(d,lo,hi)  asm("mov.b64 %0, {%1, %2};"        : "=l"(d) : "f"(lo), "f"(hi))

__global__ void fp_zero_kernel(float4* __restrict__ out, int n4) {
    int i = blockIdx.x * blockDim.x + threadIdx.x;
    if (i < n4) out[i] = make_float4(0.f, 0.f, 0.f, 0.f);
}

extern __shared__ float tile[];

__global__ void __launch_bounds__(1024, 1)
fp_main_kernel(const float* __restrict__ vol, float* __restrict__ out)
{
    const int bx  = blockIdx.x;
    const int z   = bx >> 2;
    const int p   = (bx >> 1) & 1;   // row-half phase
    const int vg  = bx & 1;          // view group of 8
    const int tid = threadIdx.x;

    __shared__ float s_cos[16], s_sin[16];
    if (tid < 16) {
        float unit = (float)(M_PI / 16.0);
        float mu   = (float)(M_PI / 180.0);
        float a = __fadd_rn(mu, __fmul_rn((float)tid, unit));
        double da = (double)a;
        s_cos[tid] = (float)cos(da);
        s_sin[tid] = (float)sin(da);
    }

    // zero whole tile, then overlay data
    for (int i = tid; i < TROWS * TS; i += 1024) tile[i] = 0.f;
    __syncthreads();

    const int nrows = 129 - p;       // phase 0: vol rows 0..128; phase 1: 128..255
    const float* __restrict__ vbase = vol + ((size_t)z << 16) + (p ? (128 * 256) : 0);
    for (int i = tid; i < nrows * 64; i += 1024) {
        int r = i >> 6, c4 = (i & 63) << 2;
        float4 v = *(const float4*)(vbase + (r << 8) + c4);
        float* d = &tile[(r + 2) * TS + 2 + c4];
        d[0] = v.x; d[1] = v.y; d[2] = v.z; d[3] = v.w;
    }
    __syncthreads();

    const int warp = tid >> 5, lane = tid & 31;
    const float lanef = (float)lane;

    const unsigned KC = 0x4B400000u - 2u;                              // tcol = floor(ix)+2
    const unsigned KR = p ? (0x4B400000u + 126u) : (0x4B400000u - 2u); // trow map per phase
    const int killRow = p ? 1 : 130;  // seam leak row (vol row 128 owned by other phase)
    const float ylo = p ? 128.f : -1.f;
    const float yhi = p ? 256.f : 128.f;

    const ull MAGIC2  = 0x4B4000004B400000ULL;  // (12582912, 12582912)
    const ull NMAGIC2 = 0xCB400000CB400000ULL;  // negated
    const ull HALF2   = 0x3F0000003F000000ULL;  // (0.5, 0.5)
    const ull NONE2   = 0xBF800000BF800000ULL;  // (-1, -1)
    const ull STEP2   = 0x4200000042000000ULL;  // (32, 32)

    // 8 views x 256 y-lines; one warp per line, lanes along x.
    for (int line = warp; line < 2048; line += 32) {
        const int v = (line >> 8) + (vg << 3);
        const int y = line & 255;
        const float c = s_cos[v], s = s_sin[v];    // s > 0 for all views
        const float yf = (float)y - 127.5f;
        const float A = fmaf(-s, yf, fmaf(-c, 127.5f, 127.5f));  // ix = c*x + A
        const float B = fmaf( c, yf, fmaf(-s, 127.5f, 127.5f));  // iy = s*x + B

        const float inv_s = __fdividef(1.f, s);
        const float inv_c = __fdividef(1.f, c);
        float r0 = (ylo  - B) * inv_s;
        float r1 = (yhi  - B) * inv_s;
        float e0 = (-1.f - A) * inv_c;
        float e1 = (256.f - A) * inv_c;
        float xlf = fmaxf(r0, fminf(e0, e1));
        float xhf = fminf(r1, fmaxf(e0, e1));
        int xlo = max(0,   (int)xlf - 2);
        int xhi = min(256, (int)xhf + 3);
        if (xlo >= xhi) continue;
        const int nb = (xhi - xlo + 31) >> 5;
        const float xcut = (float)xhi;

        ull cs2, AB2, xf2;
        PK2(cs2, c, s);
        PK2(AB2, A - 0.5f, B - 0.5f);
        float xf0 = (float)xlo + lanef;
        PK2(xf2, xf0, xf0);
        float acc = 0.f;

#define FP_BODY(TAILMASK)                                                   \
        {                                                                   \
            ull ih2, m2, f2, wh2, w2;                                       \
            FMA2(ih2, cs2, xf2, AB2);      /* (ix-.5, iy-.5) */             \
            ADD2(m2,  ih2, MAGIC2);                                         \
            ADD2(f2,  m2,  NMAGIC2);       /* (floor ix, floor iy) */       \
            FMA2(wh2, f2,  NONE2, ih2);    /* ih2 - f2 */                   \
            ADD2(w2,  wh2, HALF2);         /* (wx, wy) */                   \
            int tcol = (int)((unsigned)m2         - KC);                    \
            int trow = (int)((unsigned)(m2 >> 32) - KR);                    \
            tcol = min(max(tcol, 0), 258);                                  \
            trow = min(max(trow, 0), 131);                                  \
            float wx = __uint_as_float((unsigned)w2);                       \
            float wy = __uint_as_float((unsigned)(w2 >> 32));               \
            const float* tp = &tile[trow * TS + tcol];                      \
            float v00 = tp[0], v01 = tp[1], v10 = tp[TS], v11 = tp[TS + 1]; \
            float h0 = fmaf(wx, v01 - v00, v00);                            \
            float h1 = fmaf(wx, v11 - v10, v10);                            \
            float val = fmaf(wy, h1 - h0, h0);                              \
            val = (trow != killRow) ? val : 0.f;   /* seam kill */          \
            TAILMASK                                                        \
            acc += val;                                                     \
            ADD2(xf2, xf2, STEP2);                                          \
        }

        for (int b = 0; b < nb - 1; b++) FP_BODY()
        // peeled final block: mask x >= xhi (covers the hard x<256 cut)
        FP_BODY(val = (__uint_as_float((unsigned)xf2) < xcut) ? val : 0.f;)
#undef FP_BODY

        #pragma unroll
        for (int o = 16; o; o >>= 1) acc += __shfl_xor_sync(0xffffffffu, acc, o);
        if (lane == 0) atomicAdd(&out[(((z << 8) + y) << 4) + v], acc);
    }
}

extern "C" void kernel_launch(void* const* d_in, const int* in_sizes, int n_in,
                              void* d_out, int out_size) {
    (void)in_sizes; (void)n_in;
    cudaFuncSetAttribute(fp_main_kernel,
                         cudaFuncAttributeMaxDynamicSharedMemorySize, TILE_BYTES);
    fp_zero_kernel<<<512, 512>>>((float4*)d_out, out_size / 4);
    fp_main_kernel<<<1024, 1024, TILE_BYTES>>>((const float*)d_in[0], (float*)d_out);
}

// round 4
// speedup vs baseline: 1.1473x; 1.1473x over previous
#include <cuda_runtime.h>
#include <math.h>

#ifndef M_PI
#define M_PI 3.14159265358979323846
#endif

// Overlapping half-slice tiles, clamp-to-zero guards:
//   tile rows: 0,1 zero | 2..132 = 131 vol rows | 133,134 zero   (135 rows)
//   cols:      0,1 zero | 2..257 = vol cols 0..255 | 258,259 zero | 260 pad(0)
// Phase 0 holds vol rows 0..130   (serves floor(iy) in [-2, 131])
// Phase 1 holds vol rows 125..255 (serves floor(iy) in [123, 256])
// Lines are split at integer xs (iy ~ 127.5 crossing): p0 takes x<xs, p1 x>=xs.
#define TS    261
#define TROWS 135
#define TILE_BYTES (TROWS * TS * 4)

typedef unsigned long long ull;

#define FMA2(d,a,b,c) asm("fma.rn.f32x2 %0, %1, %2, %3;" : "=l"(d) : "l"(a), "l"(b), "l"(c))
#define ADD2(d,a,b)   asm("add.rn.f32x2 %0, %1, %2;"     : "=l"(d) : "l"(a), "l"(b))
#define PK2(d,lo,hi)  asm("mov.b64 %0, {%1, %2};"        : "=l"(d) : "f"(lo), "f"(hi))

__device__ int2 g_ranges[4096];   // per (view<<8 | y): {xlo | xs<<16, xhi}

__global__ void fp_zero_kernel(float4* __restrict__ out, int n4) {
    int i = blockIdx.x * blockDim.x + threadIdx.x;
    if (i < n4) out[i] = make_float4(0.f, 0.f, 0.f, 0.f);
}

// z-independent line geometry, computed once.
__global__ void fp_range_kernel() {
    int i = blockIdx.x * 256 + threadIdx.x;   // 0..4095
    int v = i >> 8, y = i & 255;
    float unit = (float)(M_PI / 16.0);
    float mu   = (float)(M_PI / 180.0);
    float a = __fadd_rn(mu, __fmul_rn((float)v, unit));
    double da = (double)a;
    float c = (float)cos(da), s = (float)sin(da);   // s > 0 for all views
    float yf = (float)y - 127.5f;
    float A = fmaf(-s, yf, fmaf(-c, 127.5f, 127.5f));  // ix = c*x + A
    float B = fmaf( c, yf, fmaf(-s, 127.5f, 127.5f));  // iy = s*x + B
    float inv_s = __fdividef(1.f, s);
    float inv_c = __fdividef(1.f, c);
    float xa = (-1.f  - B) * inv_s;
    float xb = (256.f - B) * inv_s;
    float e0 = (-2.f  - A) * inv_c;
    float e1 = (258.f - A) * inv_c;
    float lo = fmaxf(xa, fminf(e0, e1));
    float hi = fminf(xb, fmaxf(e0, e1));
    int xlo = max(0,   (int)floorf(lo) - 2);
    int xhi = min(256, (int)ceilf(hi) + 3);
    if (xhi < xlo) xhi = xlo;
    int xs = (int)floorf((127.5f - B) * inv_s) + 1;   // iy(xs) >= 127.5 - ~1
    xs = min(max(xs, xlo), xhi);
    g_ranges[i] = make_int2(xlo | (xs << 16), xhi);
}

extern __shared__ float tile[];

__global__ void __launch_bounds__(1024, 1)
fp_main_kernel(const float* __restrict__ vol, float* __restrict__ out)
{
    const int bx  = blockIdx.x;
    const int z   = bx >> 2;
    const int p   = (bx >> 1) & 1;   // row-half phase
    const int vg  = bx & 1;          // view group of 8
    const int tid = threadIdx.x;

    __shared__ float s_c[16], s_s[16], s_Ac[16], s_Bc[16];
    if (tid < 16) {
        float unit = (float)(M_PI / 16.0);
        float mu   = (float)(M_PI / 180.0);
        float a = __fadd_rn(mu, __fmul_rn((float)tid, unit));
        double da = (double)a;
        float c = (float)cos(da), s = (float)sin(da);
        s_c[tid] = c; s_s[tid] = s;
        s_Ac[tid] = fmaf(-c, 127.5f, 127.5f);
        s_Bc[tid] = fmaf(-s, 127.5f, 127.5f);
    }

    // zero whole tile, then overlay 131 vol rows at tile rows 2..132
    for (int i = tid; i < TROWS * TS; i += 1024) tile[i] = 0.f;
    __syncthreads();

    const int rbase = p ? 123 : -2;   // vol row = trow + 2 + (rbase)  => trow = floor(iy) - rbase
    const float* __restrict__ vbase = vol + ((size_t)z << 16) + (p ? (125 * 256) : 0);
    for (int i = tid; i < 131 * 64; i += 1024) {
        int r = i >> 6, c4 = (i & 63) << 2;
        float4 v = *(const float4*)(vbase + (r << 8) + c4);
        float* d = &tile[(r + 2) * TS + 2 + c4];
        d[0] = v.x; d[1] = v.y; d[2] = v.z; d[3] = v.w;
    }
    __syncthreads();

    const int warp = tid >> 5, lane = tid & 31;

    // magic-float bit-domain clamps and index fold
    const int LO_MIN = 0x4B400000 - 2,     LO_MAX = 0x4B400000 + 257;
    const int HI_MIN = 0x4B400000 + rbase, HI_MAX = HI_MIN + 133;
    const unsigned UOFF = (unsigned)HI_MIN * 261u + (unsigned)(0x4B400000 - 2);

    const ull MAGIC2  = 0x4B4000004B400000ULL;
    const ull NMAGIC2 = 0xCB400000CB400000ULL;
    const ull HALF2   = 0x3F0000003F000000ULL;
    const ull NONE2   = 0xBF800000BF800000ULL;
    const ull STEP2   = 0x4200000042000000ULL;  // (32, 32)

    for (int v8 = 0; v8 < 8; v8++) {
        const int v = v8 + (vg << 3);
        const float c = s_c[v], s = s_s[v], Ac = s_Ac[v], Bc = s_Bc[v];
        ull cs2; PK2(cs2, c, s);
        const int2* __restrict__ rp = &g_ranges[v << 8];

        for (int y = warp; y < 256; y += 32) {
            int2 d = __ldg(&rp[y]);
            const int xlo = d.x & 0xffff, xs = d.x >> 16, xhi = d.y;
            const int xbeg = p ? xs  : xlo;
            const int xend = p ? xhi : xs;
            if (xbeg >= xend) continue;

            const float yf = (float)y - 127.5f;
            const float A = fmaf(-s, yf, Ac) - 0.5f;
            const float B = fmaf( c, yf, Bc) - 0.5f;
            ull ab2, xf2;
            PK2(ab2, A, B);
            const float xf0 = (float)(xbeg + lane);
            PK2(xf2, xf0, xf0);
            const int nb = (xend - xbeg + 31) >> 5;
            const float xcut = (float)xend;
            float acc = 0.f;

#define FP_BODY(TAILMASK)                                                     \
            {                                                                 \
                ull ih2, m2, f2, wh2, w2;                                     \
                FMA2(ih2, cs2, xf2, ab2);      /* (ix-.5, iy-.5) */           \
                ADD2(m2,  ih2, MAGIC2);        /* magic round     */          \
                ADD2(f2,  m2,  NMAGIC2);       /* (floor ix, floor iy) */     \
                FMA2(wh2, f2,  NONE2, ih2);                                   \
                ADD2(w2,  wh2, HALF2);         /* (wx, wy) in [0,1] */        \
                int blo = (int)(unsigned)m2;                                  \
                int bhi = (int)(unsigned)(m2 >> 32);                          \
                blo = min(max(blo, LO_MIN), LO_MAX);                          \
                bhi = min(max(bhi, HI_MIN), HI_MAX);                          \
                unsigned idx = (unsigned)bhi * 261u + (unsigned)blo - UOFF;   \
                const float* tp = &tile[idx];                                 \
                float v00 = tp[0], v01 = tp[1], v10 = tp[TS], v11 = tp[TS+1]; \
                float wx = __uint_as_float((unsigned)w2);                     \
                float wy = __uint_as_float((unsigned)(w2 >> 32));             \
                float h0 = fmaf(wx, v01 - v00, v00);                          \
                float h1 = fmaf(wx, v11 - v10, v10);                          \
                float val = fmaf(wy, h1 - h0, h0);                            \
                TAILMASK                                                      \
                acc += val;                                                   \
                ADD2(xf2, xf2, STEP2);                                        \
            }

            for (int b = 0; b < nb - 1; b++) FP_BODY()
            FP_BODY(val = (__uint_as_float((unsigned)xf2) < xcut) ? val : 0.f;)
#undef FP_BODY

            #pragma unroll
            for (int o = 16; o; o >>= 1) acc += __shfl_xor_sync(0xffffffffu, acc, o);
            if (lane == 0) atomicAdd(&out[(((z << 8) + y) << 4) + v], acc);
        }
    }
}

extern "C" void kernel_launch(void* const* d_in, const int* in_sizes, int n_in,
                              void* d_out, int out_size) {
    (void)in_sizes; (void)n_in;
    cudaFuncSetAttribute(fp_main_kernel,
                         cudaFuncAttributeMaxDynamicSharedMemorySize, TILE_BYTES);
    fp_zero_kernel<<<512, 512>>>((float4*)d_out, out_size / 4);
    fp_range_kernel<<<16, 256>>>();
    fp_main_kernel<<<1024, 1024, TILE_BYTES>>>((const float*)d_in[0], (float*)d_out);
}